// round 1
// baseline (speedup 1.0000x reference)
#include <cuda_runtime.h>
#include <math.h>

#define NTOK   2048
#define DMODEL 512
#define NHEADS 8
#define DHEAD  64
#define CONDD  768
#define HH     32
#define WW     32

// ---------------- scratch (no allocation allowed) ----------------
__device__ float g_ns [2 * DMODEL];            // norm_scale
__device__ float g_xn [NTOK * DMODEL];         // rms-normed x
__device__ float g_qkv[NTOK * 3 * DMODEL];     // qkv (token-major, [3][head][64])
__device__ float g_o  [NTOK * DMODEL];         // attention output (token, head-major)

__device__ __forceinline__ float warp_sum(float v) {
    v += __shfl_xor_sync(0xffffffffu, v, 16);
    v += __shfl_xor_sync(0xffffffffu, v, 8);
    v += __shfl_xor_sync(0xffffffffu, v, 4);
    v += __shfl_xor_sync(0xffffffffu, v, 2);
    v += __shfl_xor_sync(0xffffffffu, v, 1);
    return v;
}

// ---------------- 1. norm_scale = cond @ w_cond^T + 1 ----------------
// 1024 outputs, one warp each.
__global__ void cond_scale_k(const float* __restrict__ cond,
                             const float* __restrict__ w_cond,
                             float* __restrict__ ns) {
    int gw   = (blockIdx.x * blockDim.x + threadIdx.x) >> 5;   // 0..1023
    int lane = threadIdx.x & 31;
    int n = gw >> 9, d = gw & 511;
    const float* wr = w_cond + (size_t)d * CONDD;
    const float* cr = cond   + (size_t)n * CONDD;
    float s = 0.f;
    for (int k = lane; k < CONDD; k += 32) s = fmaf(wr[k], cr[k], s);
    s = warp_sum(s);
    if (lane == 0) ns[n * DMODEL + d] = s + 1.0f;
}

// ---------------- 2. RMS norm * norm_scale ----------------
__global__ void rmsnorm_k(const float* __restrict__ x,
                          const float* __restrict__ ns,
                          float* __restrict__ xn) {
    int t = blockIdx.x;
    int n = t >> 10;
    float4 v = ((const float4*)(x + (size_t)t * DMODEL))[threadIdx.x];
    float ss = v.x*v.x + v.y*v.y + v.z*v.z + v.w*v.w;
    ss = warp_sum(ss);
    __shared__ float sred[4];
    int w = threadIdx.x >> 5, l = threadIdx.x & 31;
    if (l == 0) sred[w] = ss;
    __syncthreads();
    float tot = sred[0] + sred[1] + sred[2] + sred[3];
    float inv = rsqrtf(tot * (1.0f / DMODEL) + 1e-6f);
    float4 s4 = ((const float4*)(ns + (size_t)n * DMODEL))[threadIdx.x];
    float4 o;
    o.x = v.x * s4.x * inv; o.y = v.y * s4.y * inv;
    o.z = v.z * s4.z * inv; o.w = v.w * s4.w * inv;
    ((float4*)(xn + (size_t)t * DMODEL))[threadIdx.x] = o;
}

// ---------------- tiled fp32 GEMM: C[M][N] = A[M][K] * B[N][K]^T (+skip) ----------------
// 256 threads.  Requires BM*BK==1024 && BN*BK==1024, K % BK == 0, tiles divide M,N.
template<int BM, int BN, int BK, int TM, int TN, bool ADD>
__global__ void gemm_nt(const float* __restrict__ A, const float* __restrict__ B,
                        const float* __restrict__ S, float* __restrict__ C,
                        int M, int N, int Kd) {
    __shared__ float As[BK][BM + 4];
    __shared__ float Bs[BK][BN + 4];
    const int tid = threadIdx.x;
    const int KV = BK / 4;
    const int lr = tid / KV;
    const int lk = (tid % KV) * 4;
    const int tx = tid % (BN / TN);
    const int ty = tid / (BN / TN);
    const int m0 = blockIdx.y * BM, n0 = blockIdx.x * BN;
    const float* Ap = A + (size_t)(m0 + lr) * Kd + lk;
    const float* Bp = B + (size_t)(n0 + lr) * Kd + lk;

    float acc[TM][TN];
#pragma unroll
    for (int i = 0; i < TM; i++)
#pragma unroll
        for (int j = 0; j < TN; j++) acc[i][j] = 0.f;

    for (int kt = 0; kt < Kd; kt += BK) {
        float4 av = *(const float4*)(Ap + kt);
        float4 bv = *(const float4*)(Bp + kt);
        __syncthreads();
        As[lk+0][lr] = av.x; As[lk+1][lr] = av.y; As[lk+2][lr] = av.z; As[lk+3][lr] = av.w;
        Bs[lk+0][lr] = bv.x; Bs[lk+1][lr] = bv.y; Bs[lk+2][lr] = bv.z; Bs[lk+3][lr] = bv.w;
        __syncthreads();
#pragma unroll
        for (int kk = 0; kk < BK; kk++) {
            float a[TM], b[TN];
#pragma unroll
            for (int i = 0; i < TM; i++) a[i] = As[kk][ty * TM + i];
#pragma unroll
            for (int j = 0; j < TN; j++) b[j] = Bs[kk][tx * TN + j];
#pragma unroll
            for (int i = 0; i < TM; i++)
#pragma unroll
                for (int j = 0; j < TN; j++) acc[i][j] = fmaf(a[i], b[j], acc[i][j]);
        }
    }
#pragma unroll
    for (int i = 0; i < TM; i++) {
        int m = m0 + ty * TM + i;
#pragma unroll
        for (int j = 0; j < TN; j++) {
            int nn = n0 + tx * TN + j;
            float v = acc[i][j];
            if (ADD) v += S[(size_t)m * N + nn];
            C[(size_t)m * N + nn] = v;
        }
    }
}

// ---------------- 4. q/k L2-normalize (*sqrt(scale)) + RoPE ----------------
// one warp per (token, head); handles q and k.
__global__ void qknorm_rope_k(float* __restrict__ qkv,
                              const float* __restrict__ pos,
                              const float* __restrict__ scale) {
    int gw   = (blockIdx.x * blockDim.x + threadIdx.x) >> 5;   // 0..16383
    int lane = threadIdx.x & 31;
    int t = gw >> 3, h = gw & 7;
    float p  = pos[t];
    float sq = sqrtf(scale[h]);
    int fidx = lane & 15;
    // freqs[h][f] = pi * exp((f*8+h) * ln(10)/128)
    float freq = 3.14159265358979323846f *
                 expf((float)(fidx * 8 + h) * (2.302585092994045684f / 128.f));
    float th = p * freq;
    float c = cosf(th), sn = sinf(th);
#pragma unroll
    for (int s = 0; s < 2; s++) {   // 0: q, 1: k
        float* v = qkv + (size_t)t * (3 * DMODEL) + s * DMODEL + h * DHEAD;
        float x0 = v[lane], x1 = v[lane + 32];
        float ss = warp_sum(x0 * x0 + x1 * x1);
        float f  = sq * rsqrtf(ss + 1e-6f);
        x0 *= f; x1 *= f;
        float other = __shfl_xor_sync(0xffffffffu, x0, 16);
        float r = (lane < 16) ? (x0 * c - other * sn)   // x1*cos - x2*sin
                              : (x0 * c + other * sn);  // x2*cos + x1*sin
        v[lane]      = r;
        v[lane + 32] = x1;
    }
}

// ---------------- 5. neighborhood attention ----------------
// grid (i=32, h=8, n=2), 256 threads.  K/V for the 7 key rows x 32 cols staged in smem.
__global__ void attn_k(const float* __restrict__ qkv, float* __restrict__ o) {
    extern __shared__ float sm[];
    float* sk = sm;                  // [7][32][64]
    float* sv = sm + 7 * 32 * 64;
    const int i = blockIdx.x, h = blockIdx.y, n = blockIdx.z;
    const int si = min(max(i - 3, 0), HH - 7);
    const int tid = threadIdx.x;

    // stage K and V: 7*32 vectors of 64 floats, float4 loads
    for (int idx = tid; idx < 7 * 32 * 16; idx += 256) {
        int dg = idx & 15;
        int c  = (idx >> 4) & 31;
        int a  = idx >> 9;
        int t  = n * (HH * WW) + (si + a) * WW + c;
        const float* base = qkv + (size_t)t * (3 * DMODEL) + h * DHEAD;
        ((float4*)(sk + (a * 32 + c) * 64))[dg] = ((const float4*)(base + DMODEL))[dg];
        ((float4*)(sv + (a * 32 + c) * 64))[dg] = ((const float4*)(base + 2 * DMODEL))[dg];
    }
    __syncthreads();

    const int warp = tid >> 5, lane = tid & 31;
#pragma unroll
    for (int jq = 0; jq < 4; jq++) {
        const int j = warp * 4 + jq;
        const int t = n * (HH * WW) + i * WW + j;
        const float* qp = qkv + (size_t)t * (3 * DMODEL) + h * DHEAD;
        const float q0 = qp[lane], q1 = qp[lane + 32];
        const int sj = min(max(j - 3, 0), WW - 7);
        float m = -1e30f, l = 0.f, o0 = 0.f, o1 = 0.f;
        for (int a = 0; a < 7; a++) {
            float s[7];
#pragma unroll
            for (int b = 0; b < 7; b++) {   // 7 independent reductions -> ILP
                const float* kp = sk + (a * 32 + sj + b) * 64;
                s[b] = warp_sum(fmaf(q0, kp[lane], q1 * kp[lane + 32]));
            }
#pragma unroll
            for (int b = 0; b < 7; b++) {
                float mn   = fmaxf(m, s[b]);
                float corr = __expf(m - mn);
                float w    = __expf(s[b] - mn);
                const float* vp = sv + (a * 32 + sj + b) * 64;
                l  = l  * corr + w;
                o0 = o0 * corr + w * vp[lane];
                o1 = o1 * corr + w * vp[lane + 32];
                m = mn;
            }
        }
        float inv = 1.0f / l;
        o[(size_t)t * DMODEL + h * DHEAD + lane]      = o0 * inv;
        o[(size_t)t * DMODEL + h * DHEAD + lane + 32] = o1 * inv;
    }
}

// ---------------- launch ----------------
extern "C" void kernel_launch(void* const* d_in, const int* in_sizes, int n_in,
                              void* d_out, int out_size) {
    const float* x      = (const float*)d_in[0];
    const float* pos    = (const float*)d_in[1];
    const float* cond   = (const float*)d_in[2];
    const float* w_cond = (const float*)d_in[3];
    const float* w_qkv  = (const float*)d_in[4];
    const float* scale  = (const float*)d_in[5];
    const float* w_out  = (const float*)d_in[6];
    float* out = (float*)d_out;

    float *p_ns, *p_xn, *p_qkv, *p_o;
    cudaGetSymbolAddress((void**)&p_ns,  g_ns);
    cudaGetSymbolAddress((void**)&p_xn,  g_xn);
    cudaGetSymbolAddress((void**)&p_qkv, g_qkv);
    cudaGetSymbolAddress((void**)&p_o,   g_o);

    // 1. norm_scale
    cond_scale_k<<<128, 256>>>(cond, w_cond, p_ns);
    // 2. rms norm
    rmsnorm_k<<<NTOK, 128>>>(x, p_ns, p_xn);
    // 3. qkv = xn @ w_qkv^T   (2048 x 1536 x 512)
    gemm_nt<128, 128, 8, 8, 8, false>
        <<<dim3(1536 / 128, NTOK / 128), 256>>>(p_xn, w_qkv, nullptr, p_qkv,
                                                NTOK, 3 * DMODEL, DMODEL);
    // 4. q/k normalize + rope
    qknorm_rope_k<<<NTOK, 256>>>(p_qkv, pos, scale);
    // 5. neighborhood attention
    const int attn_smem = 7 * 32 * 64 * 2 * (int)sizeof(float);   // 114688
    cudaFuncSetAttribute(attn_k, cudaFuncAttributeMaxDynamicSharedMemorySize, attn_smem);
    attn_k<<<dim3(HH, NHEADS, 2), 256, attn_smem>>>(p_qkv, p_o);
    // 6. out = o @ w_out^T + skip   (2048 x 512 x 512)
    gemm_nt<64, 64, 16, 4, 4, true>
        <<<dim3(512 / 64, NTOK / 64), 256>>>(p_o, w_out, x, out,
                                             NTOK, DMODEL, DMODEL);
}

// round 3
// speedup vs baseline: 1.7112x; 1.7112x over previous
#include <cuda_runtime.h>
#include <cuda_bf16.h>
#include <math.h>
#include <stdint.h>

#define NTOK   2048
#define DMODEL 512
#define NHEADS 8
#define DHEAD  64
#define CONDD  768
#define HH     32
#define WW     32

// ---------------- scratch ----------------
__device__ float g_ns [2 * DMODEL];
__device__ __nv_bfloat16 g_xn_h[NTOK * DMODEL];
__device__ __nv_bfloat16 g_xn_l[NTOK * DMODEL];
__device__ float g_qkv[NTOK * 3 * DMODEL];
__device__ __nv_bfloat16 g_o_h[NTOK * DMODEL];
__device__ __nv_bfloat16 g_o_l[NTOK * DMODEL];
__device__ __nv_bfloat16 g_wq_h[3 * DMODEL * DMODEL];
__device__ __nv_bfloat16 g_wq_l[3 * DMODEL * DMODEL];
__device__ __nv_bfloat16 g_wo_h[DMODEL * DMODEL];
__device__ __nv_bfloat16 g_wo_l[DMODEL * DMODEL];

__device__ __forceinline__ float warp_sum(float v) {
    v += __shfl_xor_sync(0xffffffffu, v, 16);
    v += __shfl_xor_sync(0xffffffffu, v, 8);
    v += __shfl_xor_sync(0xffffffffu, v, 4);
    v += __shfl_xor_sync(0xffffffffu, v, 2);
    v += __shfl_xor_sync(0xffffffffu, v, 1);
    return v;
}

__device__ __forceinline__ uint32_t smem_u32(const void* p) {
    return (uint32_t)__cvta_generic_to_shared((void*)p);
}

#define SWZ(o) ((o) ^ ((((uint32_t)(o)) >> 3) & 0x70))

__device__ __forceinline__ void ldm_x4(uint32_t addr, uint32_t& r0, uint32_t& r1,
                                       uint32_t& r2, uint32_t& r3) {
    asm volatile("ldmatrix.sync.aligned.m8n8.x4.shared.b16 {%0,%1,%2,%3}, [%4];"
                 : "=r"(r0), "=r"(r1), "=r"(r2), "=r"(r3) : "r"(addr));
}
__device__ __forceinline__ void mma_bf16(float& c0, float& c1, float& c2, float& c3,
                                         uint32_t a0, uint32_t a1, uint32_t a2, uint32_t a3,
                                         uint32_t b0, uint32_t b1) {
    asm volatile(
        "mma.sync.aligned.m16n8k16.row.col.f32.bf16.bf16.f32 "
        "{%0,%1,%2,%3}, {%4,%5,%6,%7}, {%8,%9}, {%0,%1,%2,%3};"
        : "+f"(c0), "+f"(c1), "+f"(c2), "+f"(c3)
        : "r"(a0), "r"(a1), "r"(a2), "r"(a3), "r"(b0), "r"(b1));
}

// ---------------- 1. norm_scale = cond @ w_cond^T + 1 ----------------
__global__ void cond_scale_k(const float* __restrict__ cond,
                             const float* __restrict__ w_cond,
                             float* __restrict__ ns) {
    int gw   = (blockIdx.x * blockDim.x + threadIdx.x) >> 5;
    int lane = threadIdx.x & 31;
    int n = gw >> 9, d = gw & 511;
    const float* wr = w_cond + (size_t)d * CONDD;
    const float* cr = cond   + (size_t)n * CONDD;
    float s = 0.f;
    for (int k = lane; k < CONDD; k += 32) s = fmaf(wr[k], cr[k], s);
    s = warp_sum(s);
    if (lane == 0) ns[n * DMODEL + d] = s + 1.0f;
}

// ---------------- 2. RMS norm * norm_scale -> bf16 hi/lo ----------------
__global__ void rmsnorm_k(const float* __restrict__ x,
                          const float* __restrict__ ns,
                          __nv_bfloat16* __restrict__ xh,
                          __nv_bfloat16* __restrict__ xl) {
    int t = blockIdx.x;
    int n = t >> 10;
    float4 v = ((const float4*)(x + (size_t)t * DMODEL))[threadIdx.x];
    float ss = v.x*v.x + v.y*v.y + v.z*v.z + v.w*v.w;
    ss = warp_sum(ss);
    __shared__ float sred[4];
    int w = threadIdx.x >> 5, l = threadIdx.x & 31;
    if (l == 0) sred[w] = ss;
    __syncthreads();
    float tot = sred[0] + sred[1] + sred[2] + sred[3];
    float inv = rsqrtf(tot * (1.0f / DMODEL) + 1e-6f);
    float4 s4 = ((const float4*)(ns + (size_t)n * DMODEL))[threadIdx.x];
    float r0 = v.x * s4.x * inv, r1 = v.y * s4.y * inv;
    float r2 = v.z * s4.z * inv, r3 = v.w * s4.w * inv;
    __nv_bfloat16 h0 = __float2bfloat16(r0), h1 = __float2bfloat16(r1);
    __nv_bfloat16 h2 = __float2bfloat16(r2), h3 = __float2bfloat16(r3);
    __nv_bfloat16 l0 = __float2bfloat16(r0 - __bfloat162float(h0));
    __nv_bfloat16 l1 = __float2bfloat16(r1 - __bfloat162float(h1));
    __nv_bfloat16 l2 = __float2bfloat16(r2 - __bfloat162float(h2));
    __nv_bfloat16 l3 = __float2bfloat16(r3 - __bfloat162float(h3));
    size_t o = (size_t)t * DMODEL + 4 * threadIdx.x;
    ((__nv_bfloat162*)(xh + o))[0] = {h0, h1};
    ((__nv_bfloat162*)(xh + o))[1] = {h2, h3};
    ((__nv_bfloat162*)(xl + o))[0] = {l0, l1};
    ((__nv_bfloat162*)(xl + o))[1] = {l2, l3};
}

// ---------------- weight fp32 -> bf16 hi/lo ----------------
__global__ void cvt_hilo_k(const float* __restrict__ w,
                           __nv_bfloat16* __restrict__ h,
                           __nv_bfloat16* __restrict__ l, int n4) {
    int i = blockIdx.x * 256 + threadIdx.x;
    if (i >= n4) return;
    float4 v = ((const float4*)w)[i];
    __nv_bfloat16 h0 = __float2bfloat16(v.x), h1 = __float2bfloat16(v.y);
    __nv_bfloat16 h2 = __float2bfloat16(v.z), h3 = __float2bfloat16(v.w);
    __nv_bfloat16 l0 = __float2bfloat16(v.x - __bfloat162float(h0));
    __nv_bfloat16 l1 = __float2bfloat16(v.y - __bfloat162float(h1));
    __nv_bfloat16 l2 = __float2bfloat16(v.z - __bfloat162float(h2));
    __nv_bfloat16 l3 = __float2bfloat16(v.w - __bfloat162float(h3));
    ((__nv_bfloat162*)(h + 4 * (size_t)i))[0] = {h0, h1};
    ((__nv_bfloat162*)(h + 4 * (size_t)i))[1] = {h2, h3};
    ((__nv_bfloat162*)(l + 4 * (size_t)i))[0] = {l0, l1};
    ((__nv_bfloat162*)(l + 4 * (size_t)i))[1] = {l2, l3};
}

// ---------------- mma.sync GEMM: C = A@B^T (+skip), error-compensated bf16 ----------------
// 128x128 tile, 256 threads (8 warps, each 32x64).  K chunks of 64.
// smem: Ah[128][64], Al, Bh, Bl  (16KB each, XOR-swizzled 128B rows)
template<bool ADD>
__global__ void __launch_bounds__(256, 1)
gemm_mma(const __nv_bfloat16* __restrict__ Ah, const __nv_bfloat16* __restrict__ Al,
         const __nv_bfloat16* __restrict__ Bh, const __nv_bfloat16* __restrict__ Bl,
         const float* __restrict__ skip, float* __restrict__ C,
         int M, int N, int Kd) {
    extern __shared__ char smraw[];
    const uint32_t sb = smem_u32(smraw);
    const uint32_t SA_H = 0, SA_L = 16384, SB_H = 32768, SB_L = 49152;
    const int tid = threadIdx.x;
    const int wid = tid >> 5, lane = tid & 31;
    const int m0 = blockIdx.y * 128, n0 = blockIdx.x * 128;

    const __nv_bfloat16* pAh = Ah + (size_t)m0 * Kd;
    const __nv_bfloat16* pAl = Al + (size_t)m0 * Kd;
    const __nv_bfloat16* pBh = Bh + (size_t)n0 * Kd;
    const __nv_bfloat16* pBl = Bl + (size_t)n0 * Kd;
    const int rr = tid >> 3;      // 0..31
    const int ch = tid & 7;       // 16B chunk within 128B row
    const int NCH = Kd >> 6;

    float acc[2][8][4];
#pragma unroll
    for (int i = 0; i < 2; i++)
#pragma unroll
        for (int j = 0; j < 8; j++)
#pragma unroll
            for (int q = 0; q < 4; q++) acc[i][j][q] = 0.f;

    uint4 regs[16];
#define LOAD_CHUNK(c)                                                              \
    {                                                                              \
        _Pragma("unroll")                                                          \
        for (int i = 0; i < 16; i++) {                                             \
            const __nv_bfloat16* bp = (i < 4) ? pAh : (i < 8) ? pAl                \
                                     : (i < 12) ? pBh : pBl;                       \
            int r = (i & 3) * 32 + rr;                                             \
            regs[i] = *(const uint4*)(bp + (size_t)r * Kd + (c) * 64 + ch * 8);    \
        }                                                                          \
    }

    const int mw = (wid & 3) * 32;       // warp row base
    const int nw = (wid >> 2) * 64;      // warp col base

    LOAD_CHUNK(0);
    for (int c = 0; c < NCH; c++) {
#pragma unroll
        for (int i = 0; i < 16; i++) {
            int r = (i & 3) * 32 + rr;
            uint32_t tile_off = (uint32_t)(i >> 2) << 14;
            uint32_t a = sb + tile_off + SWZ((uint32_t)(r * 128 + ch * 16));
            asm volatile("st.shared.v4.b32 [%0], {%1,%2,%3,%4};"
                         :: "r"(a), "r"(regs[i].x), "r"(regs[i].y),
                            "r"(regs[i].z), "r"(regs[i].w) : "memory");
        }
        __syncthreads();
        if (c + 1 < NCH) LOAD_CHUNK(c + 1);

#pragma unroll
        for (int kk = 0; kk < 4; kk++) {
            const uint32_t colb = kk * 32 + (lane >> 4) * 16;
            const int rl = lane & 15;
            // A fragments (hi and lo), 2 m16 tiles each
            uint32_t ah[2][4], al[2][4];
#pragma unroll
            for (int mt = 0; mt < 2; mt++) {
                uint32_t off = SWZ((uint32_t)((mw + mt * 16 + rl) * 128) + colb);
                ldm_x4(sb + SA_H + off, ah[mt][0], ah[mt][1], ah[mt][2], ah[mt][3]);
                ldm_x4(sb + SA_L + off, al[mt][0], al[mt][1], al[mt][2], al[mt][3]);
            }
#pragma unroll
            for (int bt = 0; bt < 4; bt++) {
                uint32_t off = SWZ((uint32_t)((nw + bt * 16 + rl) * 128) + colb);
                uint32_t bh0, bh1, bh2, bh3, bl0, bl1, bl2, bl3;
                ldm_x4(sb + SB_H + off, bh0, bh1, bh2, bh3);
                ldm_x4(sb + SB_L + off, bl0, bl1, bl2, bl3);
#pragma unroll
                for (int mt = 0; mt < 2; mt++) {
                    float* c0 = acc[mt][bt * 2];
                    float* c1 = acc[mt][bt * 2 + 1];
                    // Ah*Bh
                    mma_bf16(c0[0], c0[1], c0[2], c0[3],
                             ah[mt][0], ah[mt][1], ah[mt][2], ah[mt][3], bh0, bh2);
                    mma_bf16(c1[0], c1[1], c1[2], c1[3],
                             ah[mt][0], ah[mt][1], ah[mt][2], ah[mt][3], bh1, bh3);
                    // Al*Bh
                    mma_bf16(c0[0], c0[1], c0[2], c0[3],
                             al[mt][0], al[mt][1], al[mt][2], al[mt][3], bh0, bh2);
                    mma_bf16(c1[0], c1[1], c1[2], c1[3],
                             al[mt][0], al[mt][1], al[mt][2], al[mt][3], bh1, bh3);
                    // Ah*Bl
                    mma_bf16(c0[0], c0[1], c0[2], c0[3],
                             ah[mt][0], ah[mt][1], ah[mt][2], ah[mt][3], bl0, bl2);
                    mma_bf16(c1[0], c1[1], c1[2], c1[3],
                             ah[mt][0], ah[mt][1], ah[mt][2], ah[mt][3], bl1, bl3);
                }
            }
        }
        __syncthreads();
    }

    // epilogue: direct stores (thread owns 2-float segments)
#pragma unroll
    for (int mt = 0; mt < 2; mt++) {
#pragma unroll
        for (int j = 0; j < 8; j++) {
            int m = m0 + mw + mt * 16 + (lane >> 2);
            int n = n0 + nw + j * 8 + (lane & 3) * 2;
            float2 v0 = {acc[mt][j][0], acc[mt][j][1]};
            float2 v1 = {acc[mt][j][2], acc[mt][j][3]};
            if (ADD) {
                float2 s0 = *(const float2*)(skip + (size_t)m * N + n);
                float2 s1 = *(const float2*)(skip + (size_t)(m + 8) * N + n);
                v0.x += s0.x; v0.y += s0.y; v1.x += s1.x; v1.y += s1.y;
            }
            *(float2*)(C + (size_t)m * N + n)       = v0;
            *(float2*)(C + (size_t)(m + 8) * N + n) = v1;
        }
    }
}

// ---------------- 4. q/k L2-normalize + RoPE ----------------
__global__ void qknorm_rope_k(float* __restrict__ qkv,
                              const float* __restrict__ pos,
                              const float* __restrict__ scale) {
    int gw   = (blockIdx.x * blockDim.x + threadIdx.x) >> 5;
    int lane = threadIdx.x & 31;
    int t = gw >> 3, h = gw & 7;
    float p  = pos[t];
    float sq = sqrtf(scale[h]);
    int fidx = lane & 15;
    float freq = 3.14159265358979323846f *
                 expf((float)(fidx * 8 + h) * (2.302585092994045684f / 128.f));
    float th = p * freq;
    float c = cosf(th), sn = sinf(th);
#pragma unroll
    for (int s = 0; s < 2; s++) {
        float* v = qkv + (size_t)t * (3 * DMODEL) + s * DMODEL + h * DHEAD;
        float x0 = v[lane], x1 = v[lane + 32];
        float ss = warp_sum(x0 * x0 + x1 * x1);
        float f  = sq * rsqrtf(ss + 1e-6f);
        x0 *= f; x1 *= f;
        float other = __shfl_xor_sync(0xffffffffu, x0, 16);
        float r = (lane < 16) ? (x0 * c - other * sn)
                              : (x0 * c + other * sn);
        v[lane]      = r;
        v[lane + 32] = x1;
    }
}

// ---------------- 5. neighborhood attention (bf16 hi/lo out) ----------------
__global__ void attn_k(const float* __restrict__ qkv,
                       __nv_bfloat16* __restrict__ oh,
                       __nv_bfloat16* __restrict__ ol) {
    extern __shared__ float sm[];
    float* sk = sm;
    float* sv = sm + 7 * 32 * 64;
    const int i = blockIdx.x, h = blockIdx.y, n = blockIdx.z;
    const int si = min(max(i - 3, 0), HH - 7);
    const int tid = threadIdx.x;

    for (int idx = tid; idx < 7 * 32 * 16; idx += 256) {
        int dg = idx & 15;
        int c  = (idx >> 4) & 31;
        int a  = idx >> 9;
        int t  = n * (HH * WW) + (si + a) * WW + c;
        const float* base = qkv + (size_t)t * (3 * DMODEL) + h * DHEAD;
        ((float4*)(sk + (a * 32 + c) * 64))[dg] = ((const float4*)(base + DMODEL))[dg];
        ((float4*)(sv + (a * 32 + c) * 64))[dg] = ((const float4*)(base + 2 * DMODEL))[dg];
    }
    __syncthreads();

    const int warp = tid >> 5, lane = tid & 31;
#pragma unroll
    for (int jq = 0; jq < 4; jq++) {
        const int j = warp * 4 + jq;
        const int t = n * (HH * WW) + i * WW + j;
        const float* qp = qkv + (size_t)t * (3 * DMODEL) + h * DHEAD;
        const float q0 = qp[lane], q1 = qp[lane + 32];
        const int sj = min(max(j - 3, 0), WW - 7);
        float m = -1e30f, l = 0.f, o0 = 0.f, o1 = 0.f;
        for (int a = 0; a < 7; a++) {
            float s[7];
#pragma unroll
            for (int b = 0; b < 7; b++) {
                const float* kp = sk + (a * 32 + sj + b) * 64;
                s[b] = warp_sum(fmaf(q0, kp[lane], q1 * kp[lane + 32]));
            }
#pragma unroll
            for (int b = 0; b < 7; b++) {
                float mn   = fmaxf(m, s[b]);
                float corr = __expf(m - mn);
                float w    = __expf(s[b] - mn);
                const float* vp = sv + (a * 32 + sj + b) * 64;
                l  = l  * corr + w;
                o0 = o0 * corr + w * vp[lane];
                o1 = o1 * corr + w * vp[lane + 32];
                m = mn;
            }
        }
        float inv = 1.0f / l;
        float r0 = o0 * inv, r1 = o1 * inv;
        __nv_bfloat16 h0 = __float2bfloat16(r0);
        __nv_bfloat16 h1 = __float2bfloat16(r1);
        size_t ob = (size_t)t * DMODEL + h * DHEAD;
        oh[ob + lane]      = h0;
        oh[ob + lane + 32] = h1;
        ol[ob + lane]      = __float2bfloat16(r0 - __bfloat162float(h0));
        ol[ob + lane + 32] = __float2bfloat16(r1 - __bfloat162float(h1));
    }
}

// ---------------- launch ----------------
extern "C" void kernel_launch(void* const* d_in, const int* in_sizes, int n_in,
                              void* d_out, int out_size) {
    const float* x      = (const float*)d_in[0];
    const float* pos    = (const float*)d_in[1];
    const float* cond   = (const float*)d_in[2];
    const float* w_cond = (const float*)d_in[3];
    const float* w_qkv  = (const float*)d_in[4];
    const float* scale  = (const float*)d_in[5];
    const float* w_out  = (const float*)d_in[6];
    float* out = (float*)d_out;

    float *p_ns, *p_qkv;
    __nv_bfloat16 *p_xh, *p_xl, *p_oh, *p_ol, *p_wqh, *p_wql, *p_woh, *p_wol;
    cudaGetSymbolAddress((void**)&p_ns,  g_ns);
    cudaGetSymbolAddress((void**)&p_qkv, g_qkv);
    cudaGetSymbolAddress((void**)&p_xh,  g_xn_h);
    cudaGetSymbolAddress((void**)&p_xl,  g_xn_l);
    cudaGetSymbolAddress((void**)&p_oh,  g_o_h);
    cudaGetSymbolAddress((void**)&p_ol,  g_o_l);
    cudaGetSymbolAddress((void**)&p_wqh, g_wq_h);
    cudaGetSymbolAddress((void**)&p_wql, g_wq_l);
    cudaGetSymbolAddress((void**)&p_woh, g_wo_h);
    cudaGetSymbolAddress((void**)&p_wol, g_wo_l);

    const int gemm_smem = 65536;
    cudaFuncSetAttribute(gemm_mma<false>, cudaFuncAttributeMaxDynamicSharedMemorySize, gemm_smem);
    cudaFuncSetAttribute(gemm_mma<true>,  cudaFuncAttributeMaxDynamicSharedMemorySize, gemm_smem);

    // 1. norm_scale
    cond_scale_k<<<128, 256>>>(cond, w_cond, p_ns);
    // weights -> bf16 hi/lo
    cvt_hilo_k<<<768, 256>>>(w_qkv, p_wqh, p_wql, 3 * DMODEL * DMODEL / 4);
    cvt_hilo_k<<<256, 256>>>(w_out, p_woh, p_wol, DMODEL * DMODEL / 4);
    // 2. rms norm -> bf16 hi/lo
    rmsnorm_k<<<NTOK, 128>>>(x, p_ns, p_xh, p_xl);
    // 3. qkv = xn @ w_qkv^T  (tensor cores via mma.sync)
    gemm_mma<false><<<dim3(1536 / 128, NTOK / 128), 256, gemm_smem>>>(
        p_xh, p_xl, p_wqh, p_wql, nullptr, p_qkv, NTOK, 3 * DMODEL, DMODEL);
    // 4. q/k normalize + rope
    qknorm_rope_k<<<NTOK, 256>>>(p_qkv, pos, scale);
    // 5. neighborhood attention
    const int attn_smem = 7 * 32 * 64 * 2 * (int)sizeof(float);
    cudaFuncSetAttribute(attn_k, cudaFuncAttributeMaxDynamicSharedMemorySize, attn_smem);
    attn_k<<<dim3(HH, NHEADS, 2), 256, attn_smem>>>(p_qkv, p_oh, p_ol);
    // 6. out = o @ w_out^T + skip
    gemm_mma<true><<<dim3(DMODEL / 128, NTOK / 128), 256, gemm_smem>>>(
        p_oh, p_ol, p_woh, p_wol, x, out, NTOK, DMODEL, DMODEL);
}